// round 2
// baseline (speedup 1.0000x reference)
#include <cuda_runtime.h>
#include <cstdint>

#define N_NODES 50000
#define N_EDGES 800000
// feature dims
#define F_IN   128
#define F_HID  64
#define F_OUT  40

// ---------------- scratch (device globals: no allocation allowed) ----------
__device__ float g_buf1[N_NODES * 64];   // h' (gemm out, dinv-scaled)
__device__ float g_buf2[N_NODES * 64];   // agg / activation layer 1
__device__ float g_buf3[N_NODES * 64];   // agg / activation layer 2
__device__ int   g_deg [N_NODES];
__device__ float g_dinv[N_NODES];

// ---------------- degree / norm --------------------------------------------
__global__ void deg_init_k(int* __restrict__ deg) {
    int i = blockIdx.x * blockDim.x + threadIdx.x;
    if (i < N_NODES) deg[i] = 1;              // self loop
}

__global__ void deg_count_k(const int* __restrict__ dst, int* __restrict__ deg) {
    int e = blockIdx.x * blockDim.x + threadIdx.x;
    if (e < N_EDGES) atomicAdd(&deg[dst[e]], 1);
}

__global__ void dinv_k(const int* __restrict__ deg, float* __restrict__ dinv) {
    int i = blockIdx.x * blockDim.x + threadIdx.x;
    if (i < N_NODES) dinv[i] = rsqrtf((float)deg[i]);
}

// ---------------- GEMM: C = (A[N,M] @ W[M,K]) * dinv[row], dual store ------
// BM=64, BN=64(pred for K=40), BK=16, 256 threads, 4x4 micro-tile.
__global__ __launch_bounds__(256)
void gemm_scaled_k(const float* __restrict__ A, const float* __restrict__ W,
                   const float* __restrict__ dinv,
                   float* __restrict__ Ch, float* __restrict__ Ca,
                   int M, int K)
{
    __shared__ float As[64][16];
    __shared__ float Ws[16][64];

    const int tid = threadIdx.x;
    const int tx  = tid & 15;        // 0..15 : col group (4 cols)
    const int ty  = tid >> 4;        // 0..15 : row group (4 rows)
    const int n0  = blockIdx.x * 64;

    const int aRow = tid >> 2;            // 0..63
    const int aCol = (tid & 3) << 2;      // 0,4,8,12
    const int wRow = tid >> 4;            // 0..15
    const int wCol = (tid & 15) << 2;     // 0..60

    float acc[4][4] = {};

    for (int k0 = 0; k0 < M; k0 += 16) {
        float4 av = make_float4(0.f, 0.f, 0.f, 0.f);
        if (n0 + aRow < N_NODES)
            av = *(const float4*)(A + (size_t)(n0 + aRow) * M + k0 + aCol);
        *(float4*)&As[aRow][aCol] = av;

        float4 wv = make_float4(0.f, 0.f, 0.f, 0.f);
        if (wCol < K)
            wv = *(const float4*)(W + (size_t)(k0 + wRow) * K + wCol);
        *(float4*)&Ws[wRow][wCol] = wv;

        __syncthreads();

        #pragma unroll
        for (int k = 0; k < 16; k++) {
            float  ra0 = As[(ty << 2) + 0][k];
            float  ra1 = As[(ty << 2) + 1][k];
            float  ra2 = As[(ty << 2) + 2][k];
            float  ra3 = As[(ty << 2) + 3][k];
            float4 rb  = *(const float4*)&Ws[k][tx << 2];
            acc[0][0] += ra0 * rb.x; acc[0][1] += ra0 * rb.y;
            acc[0][2] += ra0 * rb.z; acc[0][3] += ra0 * rb.w;
            acc[1][0] += ra1 * rb.x; acc[1][1] += ra1 * rb.y;
            acc[1][2] += ra1 * rb.z; acc[1][3] += ra1 * rb.w;
            acc[2][0] += ra2 * rb.x; acc[2][1] += ra2 * rb.y;
            acc[2][2] += ra2 * rb.z; acc[2][3] += ra2 * rb.w;
            acc[3][0] += ra3 * rb.x; acc[3][1] += ra3 * rb.y;
            acc[3][2] += ra3 * rb.z; acc[3][3] += ra3 * rb.w;
        }
        __syncthreads();
    }

    const int colBase = tx << 2;
    if (colBase < K) {                    // K % 4 == 0 always (64 or 40)
        #pragma unroll
        for (int i = 0; i < 4; i++) {
            int row = n0 + (ty << 2) + i;
            if (row < N_NODES) {
                float s = dinv[row];
                float4 v;
                v.x = acc[i][0] * s; v.y = acc[i][1] * s;
                v.z = acc[i][2] * s; v.w = acc[i][3] * s;
                size_t off = (size_t)row * K + colBase;
                *(float4*)(Ch + off) = v;
                *(float4*)(Ca + off) = v;      // self-loop init of agg
            }
        }
    }
}

// ---------------- edge scatter: agg[dst] += h'[src]  (vector RED) ----------
template<int F>
__global__ __launch_bounds__(256)
void scatter_k(const int* __restrict__ src, const int* __restrict__ dst,
               const float* __restrict__ h, float* __restrict__ agg)
{
    constexpr int FP4 = F / 4;
    unsigned idx = blockIdx.x * blockDim.x + threadIdx.x;
    if (idx >= (unsigned)N_EDGES * FP4) return;
    unsigned e = idx / FP4;
    unsigned j = (idx - e * FP4) << 2;
    int s = src[e];
    int d = dst[e];
    float4 v = *(const float4*)(h + (size_t)s * F + j);
    float* p = agg + (size_t)d * F + j;
    asm volatile("red.global.add.v4.f32 [%0], {%1, %2, %3, %4};"
                 :: "l"(p), "f"(v.x), "f"(v.y), "f"(v.z), "f"(v.w)
                 : "memory");
}

// ---------------- epilogue: a = (relu?)(dinv[i]*a + b[col]), in place ------
template<int F, bool RELU>
__global__ __launch_bounds__(256)
void epilogue_k(float* __restrict__ a, const float* __restrict__ dinv,
                const float* __restrict__ bias)
{
    constexpr int FP4 = F / 4;
    unsigned idx = blockIdx.x * blockDim.x + threadIdx.x;
    if (idx >= (unsigned)N_NODES * FP4) return;
    unsigned i = idx / FP4;
    unsigned j = (idx - i * FP4) << 2;
    float s = dinv[i];
    float4 v = *(float4*)(a + (size_t)i * F + j);
    float4 b = *(const float4*)(bias + j);
    v.x = fmaf(v.x, s, b.x);
    v.y = fmaf(v.y, s, b.y);
    v.z = fmaf(v.z, s, b.z);
    v.w = fmaf(v.w, s, b.w);
    if (RELU) {
        v.x = fmaxf(v.x, 0.f); v.y = fmaxf(v.y, 0.f);
        v.z = fmaxf(v.z, 0.f); v.w = fmaxf(v.w, 0.f);
    }
    *(float4*)(a + (size_t)i * F + j) = v;
}

// ---------------- launch ---------------------------------------------------
extern "C" void kernel_launch(void* const* d_in, const int* in_sizes, int n_in,
                              void* d_out, int out_size)
{
    const float* x  = (const float*)d_in[0];
    const int*   ei = (const int*)  d_in[1];
    const float* W1 = (const float*)d_in[2];
    const float* b1 = (const float*)d_in[3];
    const float* W2 = (const float*)d_in[4];
    const float* b2 = (const float*)d_in[5];
    const float* W3 = (const float*)d_in[6];
    const float* b3 = (const float*)d_in[7];
    float* out = (float*)d_out;

    const int* src = ei;              // edge_index[0]
    const int* dst = ei + N_EDGES;    // edge_index[1]

    float *buf1, *buf2, *buf3, *dinv;
    int* deg;
    cudaGetSymbolAddress((void**)&buf1, g_buf1);
    cudaGetSymbolAddress((void**)&buf2, g_buf2);
    cudaGetSymbolAddress((void**)&buf3, g_buf3);
    cudaGetSymbolAddress((void**)&dinv, g_dinv);
    cudaGetSymbolAddress((void**)&deg,  g_deg);

    const int TPB = 256;
    const int nodeBlocks  = (N_NODES + TPB - 1) / TPB;
    const int edgeBlocks  = (N_EDGES + TPB - 1) / TPB;
    const int gemmBlocks  = (N_NODES + 63) / 64;
    const int sc64Blocks  = ((unsigned)N_EDGES * 16 + TPB - 1) / TPB;
    const int sc40Blocks  = ((unsigned)N_EDGES * 10 + TPB - 1) / TPB;
    const int ep64Blocks  = ((unsigned)N_NODES * 16 + TPB - 1) / TPB;
    const int ep40Blocks  = ((unsigned)N_NODES * 10 + TPB - 1) / TPB;

    // normalization coefficients
    deg_init_k <<<nodeBlocks, TPB>>>(deg);
    deg_count_k<<<edgeBlocks, TPB>>>(dst, deg);
    dinv_k     <<<nodeBlocks, TPB>>>(deg, dinv);

    // ---- layer 1: x[50000,128] @ W1[128,64] ----
    gemm_scaled_k<<<gemmBlocks, TPB>>>(x, W1, dinv, buf1, buf2, F_IN, F_HID);
    scatter_k<F_HID><<<sc64Blocks, TPB>>>(src, dst, buf1, buf2);
    epilogue_k<F_HID, true><<<ep64Blocks, TPB>>>(buf2, dinv, b1);

    // ---- layer 2: z1[50000,64] @ W2[64,64] ----
    gemm_scaled_k<<<gemmBlocks, TPB>>>(buf2, W2, dinv, buf1, buf3, F_HID, F_HID);
    scatter_k<F_HID><<<sc64Blocks, TPB>>>(src, dst, buf1, buf3);
    epilogue_k<F_HID, true><<<ep64Blocks, TPB>>>(buf3, dinv, b2);

    // ---- layer 3: z2[50000,64] @ W3[64,40] -> d_out ----
    gemm_scaled_k<<<gemmBlocks, TPB>>>(buf3, W3, dinv, buf1, out, F_HID, F_OUT);
    scatter_k<F_OUT><<<sc40Blocks, TPB>>>(src, dst, buf1, out);
    epilogue_k<F_OUT, false><<<ep40Blocks, TPB>>>(out, dinv, b3);
}

// round 4
// speedup vs baseline: 1.4869x; 1.4869x over previous
#include <cuda_runtime.h>
#include <cstdint>

#define N_NODES 50000
#define N_EDGES 800000
#define F_IN   128
#define F_HID  64
#define F_OUT  40
#define SCAN_B 1024
#define SCAN_NB ((N_NODES + SCAN_B - 1) / SCAN_B)   // 49

// ---------------- scratch (device globals: no allocation allowed) ----------
__device__ float g_h[N_NODES * 64];      // GEMM output h' (dinv-prescaled)
__device__ float g_z[N_NODES * 64];      // activation buffer
__device__ int   g_dege[N_NODES];        // edge-only degree (no self loop)
__device__ int   g_cursor[N_NODES];
__device__ int   g_rowstart[N_NODES];
__device__ int   g_csrc[N_EDGES];
__device__ int   g_bsum[SCAN_NB];
__device__ float g_dinv[N_NODES];

// ---------------- degree / norm / CSR build --------------------------------
__global__ void deg_init_k(int* __restrict__ dege) {
    int i = blockIdx.x * blockDim.x + threadIdx.x;
    if (i < N_NODES) dege[i] = 0;
}

__global__ void deg_count_k(const int* __restrict__ dst, int* __restrict__ dege) {
    int e = blockIdx.x * blockDim.x + threadIdx.x;
    if (e < N_EDGES) atomicAdd(&dege[dst[e]], 1);
}

// dinv = rsqrt(deg_e + 1) ; also zero the fill cursor
__global__ void dinv_k(const int* __restrict__ dege, float* __restrict__ dinv,
                       int* __restrict__ cursor) {
    int i = blockIdx.x * blockDim.x + threadIdx.x;
    if (i < N_NODES) {
        dinv[i] = rsqrtf((float)(dege[i] + 1));
        cursor[i] = 0;
    }
}

// block-local exclusive scan (Hillis-Steele, 1024 wide)
__global__ __launch_bounds__(SCAN_B)
void scan1_k(const int* __restrict__ dege, int* __restrict__ rowstart,
             int* __restrict__ bsum) {
    __shared__ int s[SCAN_B];
    int t = threadIdx.x;
    int g = blockIdx.x * SCAN_B + t;
    int v = (g < N_NODES) ? dege[g] : 0;
    s[t] = v;
    __syncthreads();
    #pragma unroll
    for (int off = 1; off < SCAN_B; off <<= 1) {
        int x = (t >= off) ? s[t - off] : 0;
        __syncthreads();
        s[t] += x;
        __syncthreads();
    }
    if (g < N_NODES) rowstart[g] = s[t] - v;     // exclusive
    if (t == SCAN_B - 1) bsum[blockIdx.x] = s[t];
}

__global__ void scan2_k(int* __restrict__ bsum) {
    __shared__ int s[64];
    int t = threadIdx.x;
    int v = (t < SCAN_NB) ? bsum[t] : 0;
    s[t] = v;
    __syncthreads();
    #pragma unroll
    for (int off = 1; off < 64; off <<= 1) {
        int x = (t >= off) ? s[t - off] : 0;
        __syncthreads();
        s[t] += x;
        __syncthreads();
    }
    if (t < SCAN_NB) bsum[t] = s[t] - v;         // exclusive block offsets
}

__global__ __launch_bounds__(SCAN_B)
void scan3_k(int* __restrict__ rowstart, const int* __restrict__ bsum) {
    int t = threadIdx.x;
    int g = blockIdx.x * SCAN_B + t;
    if (g < N_NODES) rowstart[g] += bsum[blockIdx.x];
}

__global__ void fill_k(const int* __restrict__ src, const int* __restrict__ dst,
                       const int* __restrict__ rowstart, int* __restrict__ cursor,
                       int* __restrict__ csrc) {
    int e = blockIdx.x * blockDim.x + threadIdx.x;
    if (e < N_EDGES) {
        int d = dst[e];
        int pos = rowstart[d] + atomicAdd(&cursor[d], 1);
        csrc[pos] = src[e];
    }
}

// ---------------- GEMM: C = (A[N,M] @ W[M,K]) * dinv[row] ------------------
// BM=128, BN=64, BK=16, 256 threads, 8x4 micro-tile. A-tile stored transposed.
__global__ __launch_bounds__(256)
void gemm_scaled_k(const float* __restrict__ A, const float* __restrict__ W,
                   const float* __restrict__ dinv, float* __restrict__ C,
                   int M, int K)
{
    __shared__ float As[16][132];   // [k][row], padded against store conflicts
    __shared__ float Ws[16][64];    // [k][col]

    const int tid = threadIdx.x;
    const int tx  = tid & 15;            // col group: cols tx*4 .. +3
    const int ty  = tid >> 4;            // row group: rows ty*8 .. +7
    const int n0  = blockIdx.x * 128;

    const int aRow = tid >> 2;           // 0..63
    const int aCol = (tid & 3) << 2;     // 0,4,8,12
    const int wRow = tid >> 4;           // 0..15
    const int wCol = (tid & 15) << 2;    // 0..60

    float acc[8][4] = {};

    for (int k0 = 0; k0 < M; k0 += 16) {
        #pragma unroll
        for (int hh = 0; hh < 2; hh++) {
            int row = aRow + hh * 64;
            float4 av = make_float4(0.f, 0.f, 0.f, 0.f);
            if (n0 + row < N_NODES)
                av = *(const float4*)(A + (size_t)(n0 + row) * M + k0 + aCol);
            As[aCol + 0][row] = av.x;
            As[aCol + 1][row] = av.y;
            As[aCol + 2][row] = av.z;
            As[aCol + 3][row] = av.w;
        }
        float4 wv = make_float4(0.f, 0.f, 0.f, 0.f);
        if (wCol < K)
            wv = *(const float4*)(W + (size_t)(k0 + wRow) * K + wCol);
        *(float4*)&Ws[wRow][wCol] = wv;

        __syncthreads();

        #pragma unroll
        for (int k = 0; k < 16; k++) {
            float4 a0 = *(const float4*)&As[k][ty * 8];
            float4 a1 = *(const float4*)&As[k][ty * 8 + 4];
            float4 b  = *(const float4*)&Ws[k][tx * 4];
            float ar[8] = {a0.x, a0.y, a0.z, a0.w, a1.x, a1.y, a1.z, a1.w};
            #pragma unroll
            for (int i = 0; i < 8; i++) {
                acc[i][0] += ar[i] * b.x;
                acc[i][1] += ar[i] * b.y;
                acc[i][2] += ar[i] * b.z;
                acc[i][3] += ar[i] * b.w;
            }
        }
        __syncthreads();
    }

    const int colBase = tx << 2;
    if (colBase < K) {
        #pragma unroll
        for (int i = 0; i < 8; i++) {
            int row = n0 + ty * 8 + i;
            if (row < N_NODES) {
                float s = dinv[row];
                float4 v;
                v.x = acc[i][0] * s; v.y = acc[i][1] * s;
                v.z = acc[i][2] * s; v.w = acc[i][3] * s;
                *(float4*)(C + (size_t)row * K + colBase) = v;
            }
        }
    }
}

// ---------------- fused CSR aggregation + epilogue -------------------------
// z[d] = act( dinv[d] * ( h'[d] + sum_{s in N(d)} h'[s] ) + bias )
// 16 consecutive threads per node, each owns one float4 column slice.
// Neighbor index is prefetched one iteration ahead to hide the
// index->row dependent-load chain.
template<int F, bool RELU>
__global__ __launch_bounds__(256)
void agg_fused_k(const float* __restrict__ h, const int* __restrict__ rowstart,
                 const int* __restrict__ dege, const int* __restrict__ csrc,
                 const float* __restrict__ dinv, const float* __restrict__ bias,
                 float* __restrict__ z)
{
    unsigned t = blockIdx.x * blockDim.x + threadIdx.x;
    unsigned node = t >> 4;
    unsigned j = (t & 15) << 2;
    if (node >= N_NODES) return;
    const bool active = (j < F);

    float4 acc = make_float4(0.f, 0.f, 0.f, 0.f);
    if (active)
        acc = *(const float4*)(h + (size_t)node * F + j);   // self loop

    int i   = rowstart[node];
    int end = i + dege[node];
    int s_next = (i < end) ? __ldg(&csrc[i]) : 0;
    for (; i < end; i++) {
        int s = s_next;
        if (i + 1 < end) s_next = __ldg(&csrc[i + 1]);
        if (active) {
            float4 v = __ldg((const float4*)(h + (size_t)s * F + j));
            acc.x += v.x; acc.y += v.y; acc.z += v.z; acc.w += v.w;
        }
    }

    if (active) {
        float sc = dinv[node];
        float4 b = *(const float4*)(bias + j);
        acc.x = fmaf(acc.x, sc, b.x);
        acc.y = fmaf(acc.y, sc, b.y);
        acc.z = fmaf(acc.z, sc, b.z);
        acc.w = fmaf(acc.w, sc, b.w);
        if (RELU) {
            acc.x = fmaxf(acc.x, 0.f); acc.y = fmaxf(acc.y, 0.f);
            acc.z = fmaxf(acc.z, 0.f); acc.w = fmaxf(acc.w, 0.f);
        }
        *(float4*)(z + (size_t)node * F + j) = acc;
    }
}

// ---------------- launch ---------------------------------------------------
extern "C" void kernel_launch(void* const* d_in, const int* in_sizes, int n_in,
                              void* d_out, int out_size)
{
    const float* x  = (const float*)d_in[0];
    const int*   ei = (const int*)  d_in[1];
    const float* W1 = (const float*)d_in[2];
    const float* b1 = (const float*)d_in[3];
    const float* W2 = (const float*)d_in[4];
    const float* b2 = (const float*)d_in[5];
    const float* W3 = (const float*)d_in[6];
    const float* b3 = (const float*)d_in[7];
    float* out = (float*)d_out;

    const int* src = ei;              // edge_index[0]
    const int* dst = ei + N_EDGES;    // edge_index[1]

    float *h, *z, *dinv;
    int *dege, *cursor, *rowstart, *csrc, *bsum;
    cudaGetSymbolAddress((void**)&h,        g_h);
    cudaGetSymbolAddress((void**)&z,        g_z);
    cudaGetSymbolAddress((void**)&dinv,     g_dinv);
    cudaGetSymbolAddress((void**)&dege,     g_dege);
    cudaGetSymbolAddress((void**)&cursor,   g_cursor);
    cudaGetSymbolAddress((void**)&rowstart, g_rowstart);
    cudaGetSymbolAddress((void**)&csrc,     g_csrc);
    cudaGetSymbolAddress((void**)&bsum,     g_bsum);

    const int TPB = 256;
    const int nodeBlocks = (N_NODES + TPB - 1) / TPB;
    const int edgeBlocks = (N_EDGES + TPB - 1) / TPB;
    const int gemmBlocks = (N_NODES + 127) / 128;
    const int aggBlocks  = ((unsigned)N_NODES * 16 + TPB - 1) / TPB;

    // ---- CSR build + normalization ----
    deg_init_k <<<nodeBlocks, TPB>>>(dege);
    deg_count_k<<<edgeBlocks, TPB>>>(dst, dege);
    dinv_k     <<<nodeBlocks, TPB>>>(dege, dinv, cursor);
    scan1_k    <<<SCAN_NB, SCAN_B>>>(dege, rowstart, bsum);
    scan2_k    <<<1, 64>>>(bsum);
    scan3_k    <<<SCAN_NB, SCAN_B>>>(rowstart, bsum);
    fill_k     <<<edgeBlocks, TPB>>>(src, dst, rowstart, cursor, csrc);

    // ---- layer 1: x[50000,128] @ W1[128,64] ----
    gemm_scaled_k<<<gemmBlocks, TPB>>>(x, W1, dinv, h, F_IN, F_HID);
    agg_fused_k<F_HID, true><<<aggBlocks, TPB>>>(h, rowstart, dege, csrc, dinv, b1, z);

    // ---- layer 2: z1 @ W2[64,64] ----
    gemm_scaled_k<<<gemmBlocks, TPB>>>(z, W2, dinv, h, F_HID, F_HID);
    agg_fused_k<F_HID, true><<<aggBlocks, TPB>>>(h, rowstart, dege, csrc, dinv, b2, z);

    // ---- layer 3: z2 @ W3[64,40] -> d_out ----
    gemm_scaled_k<<<gemmBlocks, TPB>>>(z, W3, dinv, h, F_HID, F_OUT);
    agg_fused_k<F_OUT, false><<<aggBlocks, TPB>>>(h, rowstart, dege, csrc, dinv, b3, out);
}